// round 16
// baseline (speedup 1.0000x reference)
#include <cuda_runtime.h>
#include <cuda_fp16.h>
#include <cstdint>

#define DINLINE __device__ __forceinline__

// ---------------------------------------------------------------------------
// Problem constants
// ---------------------------------------------------------------------------
constexpr int BATCH = 8192;
constexpr int HID   = 1024;
constexpr int KDIM  = 2048;               // I + H
constexpr int NTOT  = 4096;               // 4 gates * HID

constexpr int BM  = 64;                   // CTA M tile
constexpr int BN  = 128;                  // CTA N tile (4 gates x 32 h-cols)
constexpr int BNH = 32;                   // h-columns per CTA
constexpr int KC  = 64;                   // K per chunk (64 fp16 = 128 B/row)
constexpr int KI  = KDIM / KC;            // 32 chunks

constexpr int NSTAGE      = 4;            // 4 stages -> 2-chunk wait slack
constexpr int STAGE_A     = BM * 128;     // 8 KB
constexpr int STAGE_B     = BN * 128;     // 16 KB
constexpr int STAGE_BYTES = STAGE_A + STAGE_B;            // 24 KB
constexpr int DYN_SMEM    = 1024 + NSTAGE * STAGE_BYTES;  // ~97 KB -> 2 CTAs/SM

// Merged prep kernel block split
constexpr int PACKA_BLOCKS = (BATCH * KDIM / 8) / 256;    // 8192 (8 halves/thr)
constexpr int PACKB_BLOCKS = (KDIM / 32) * (NTOT / 32);   // 8192

// Scratch (allocation-free rule: __device__ globals)
__device__ __half g_A[(size_t)BATCH * KDIM];   // 32 MB: fp16 [x|h]
__device__ __half g_B[(size_t)NTOT * KDIM];    // 16 MB: fp16 W^T (K-major)
// 48 MB total: L2-resident (measured DRAM 5%).

// ---------------------------------------------------------------------------
// PTX helpers (base PTX only: cp.async / ldmatrix / mma.sync)
// ---------------------------------------------------------------------------
DINLINE uint32_t smem_u32(const void* p) {
    uint32_t a;
    asm("{ .reg .u64 t; cvta.to.shared.u64 t, %1; cvt.u32.u64 %0, t; }"
        : "=r"(a) : "l"(p));
    return a;
}

DINLINE void cp16_cg(uint32_t dst, const void* src) {   // streaming (A)
    asm volatile("cp.async.cg.shared.global [%0], [%1], 16;"
                 :: "r"(dst), "l"(src) : "memory");
}
DINLINE void cp16_ca(uint32_t dst, const void* src) {   // L1-allocating (B:
    asm volatile("cp.async.ca.shared.global [%0], [%1], 16;"  // shared by the
                 :: "r"(dst), "l"(src) : "memory");           // 2 same-nh0 CTAs)
}
DINLINE void cp_commit() { asm volatile("cp.async.commit_group;" ::: "memory"); }
template <int N> DINLINE void cp_wait() {
    asm volatile("cp.async.wait_group %0;" :: "n"(N) : "memory");
}

DINLINE void l2_prefetch(const void* p) {
    asm volatile("prefetch.global.L2 [%0];" :: "l"(p));
}

// ldmatrix.x4 on fp16: lane l of each 8x8 b16 matrix gets the 4B word
// [row=l/4][pair=l%4] -- exactly one fp16 mma fragment register.
DINLINE void ldsm4(uint32_t* r, uint32_t addr) {
    asm volatile("ldmatrix.sync.aligned.m8n8.x4.shared.b16 {%0,%1,%2,%3}, [%4];"
                 : "=r"(r[0]), "=r"(r[1]), "=r"(r[2]), "=r"(r[3]) : "r"(addr));
}

// fp16 m16n8k16: 2048 MACs/instr, f32 accumulate.
DINLINE void mma_f16(float* d, const uint32_t* a, const uint32_t* b) {
    asm("mma.sync.aligned.m16n8k16.row.col.f32.f16.f16.f32 "
        "{%0,%1,%2,%3}, {%4,%5,%6,%7}, {%8,%9}, {%0,%1,%2,%3};"
        : "+f"(d[0]), "+f"(d[1]), "+f"(d[2]), "+f"(d[3])
        : "r"(a[0]), "r"(a[1]), "r"(a[2]), "r"(a[3]), "r"(b[0]), "r"(b[1]));
}

DINLINE uint32_t SWZ(uint32_t b) { return b ^ ((b >> 3) & 0x70); }

DINLINE float sigm(float x)  { return __fdividef(1.0f, 1.0f + __expf(-x)); }
DINLINE float tanhe(float x) { return 1.0f - __fdividef(2.0f, __expf(2.0f * x) + 1.0f); }

// ---------------------------------------------------------------------------
// Merged prep kernel: blocks [0, PACKA_BLOCKS) pack A=[x|h] -> fp16; the rest
// pack B=W^T (K-major) -> fp16. fp16 rn rounding == tf32 mantissa -> error
// profile identical to the measured 2.01e-4 config.
// ---------------------------------------------------------------------------
__global__ void pack_ab_kernel(const float* __restrict__ x,
                               const float* __restrict__ h,
                               const float* __restrict__ Wx,
                               const float* __restrict__ Wh) {
    const int tid = threadIdx.x;            // 256 threads
    if (blockIdx.x < PACKA_BLOCKS) {
        // ---- pack A: 8 floats -> 8 halves (16B store) ----
        size_t v = (size_t)blockIdx.x * 256 + tid;   // 8-half group index
        int m = (int)(v >> 8);              // 256 groups per 2048-wide row
        int q = (int)(v & 255);
        const float* src = (q < 128) ? (x + (size_t)m * HID + (size_t)q * 8)
                                     : (h + (size_t)m * HID + (size_t)(q - 128) * 8);
        float4 f0 = ((const float4*)src)[0];
        float4 f1 = ((const float4*)src)[1];
        __half2 r[4];
        r[0] = __floats2half2_rn(f0.x, f0.y);
        r[1] = __floats2half2_rn(f0.z, f0.w);
        r[2] = __floats2half2_rn(f1.x, f1.y);
        r[3] = __floats2half2_rn(f1.z, f1.w);
        *(uint4*)(g_A + v * 8) = *(const uint4*)r;
    } else {
        // ---- pack B: fp16-round + transpose W -> [N, K] ----
        __shared__ float tile[32][33];
        int bb = blockIdx.x - PACKA_BLOCKS;
        int k0 = (bb & 63) * 32;            // 64 k-blocks
        int n0 = (bb >> 6) * 32;            // 128 n-blocks
        int tx = tid & 31, ty = tid >> 5;   // (32, 8)
#pragma unroll
        for (int i = 0; i < 32; i += 8) {
            int k = k0 + ty + i;
            float v = (k < 1024) ? Wx[(size_t)k * NTOT + n0 + tx]
                                 : Wh[(size_t)(k - 1024) * NTOT + n0 + tx];
            tile[ty + i][tx] = v;
        }
        __syncthreads();
#pragma unroll
        for (int i = 0; i < 32; i += 8) {
            int n = n0 + ty + i;
            g_B[(size_t)n * KDIM + k0 + tx] = __float2half_rn(tile[tx][ty + i]);
        }
    }
}

// ---------------------------------------------------------------------------
// Fused GEMM + LSTM epilogue (cp.async + ldmatrix + mma.sync.f16)
// 4-STAGE single-barrier mainloop: wait<2> (2-chunk slack -> never blocks) ->
// sync -> issue chunk k+3 into the stage freed at iter k-1 -> compute k.
// Trades the neutral 3rd CTA (R14 vs R12) for prefetch depth.
// ---------------------------------------------------------------------------
// Grid = (m fastest, nh slowest): all 128 CTAs of one nh0 column reuse the
// SAME B slice in L2 (and the 2 co-resident CTAs share B via L1 thanks to
// cp.async.ca) while A streams once.
//
// B smem row r (0..127) holds global N row:
//   n(r) = ((r>>4)&3)*1024 + nh0 + (r&15) + ((r>>6)&1)*16
// so each warp's 64 columns = {i,f,g,o} x 16 h-cols and each THREAD holds all
// four gate values for its (m, hcol) pairs -> register-only LSTM epilogue.
DINLINE void load_stage(uint32_t sbase, int s, int kc, int m0, int nh0, int tid) {
    const uint32_t sA = sbase + (uint32_t)s * STAGE_BYTES;
    const uint32_t sB = sA + STAGE_A;
    const __half* gA = g_A + (size_t)m0 * KDIM + (size_t)kc * KC;
    const __half* gB = g_B + (size_t)kc * KC;
#pragma unroll
    for (int i = 0; i < 4; i++) {          // A: 64 rows x 128B (64 fp16)
        int ch = tid + (i << 7);
        int r = ch >> 3, kb = ch & 7;
        uint32_t off = (uint32_t)(r * 128 + kb * 16);
        cp16_cg(sA + SWZ(off), (const char*)(gA + (size_t)r * KDIM) + kb * 16);
    }
#pragma unroll
    for (int i = 0; i < 8; i++) {          // B: 128 gate-interleaved N rows x 128B
        int ch = tid + (i << 7);
        int r = ch >> 3, kb = ch & 7;
        int n = ((r >> 4) & 3) * 1024 + nh0 + (r & 15) + ((r >> 6) & 1) * 16;
        uint32_t off = (uint32_t)(r * 128 + kb * 16);
        cp16_ca(sB + SWZ(off), (const char*)(gB + (size_t)n * KDIM) + kb * 16);
    }
}

__global__ void __launch_bounds__(128, 2)
lstm_gemm_kernel(const float* __restrict__ c_in, const float* __restrict__ bx,
                 float* __restrict__ h_out, float* __restrict__ c_out) {
    extern __shared__ __align__(16) char dynsmem[];
    __shared__ float s_bias[BN];

    const int tid = threadIdx.x;
    const int wid = tid >> 5;
    const int lid = tid & 31;
    const int m0  = blockIdx.x * BM;    // m fastest (proven best)
    const int nh0 = blockIdx.y * BNH;

    const int wm0 = (wid >> 1) * 32;   // warp M offset (2x2 warp grid, 32x64 tiles)
    const int wn0 = (wid & 1) * 64;    // warp N offset (smem B column space)

    uint32_t sbase = (smem_u32(dynsmem) + 1023u) & ~1023u;

    // bias cache, ordered identically to B smem columns
    {
        int r = tid;
        int n = ((r >> 4) & 3) * 1024 + nh0 + (r & 15) + ((r >> 6) & 1) * 16;
        s_bias[r] = bx[n];
    }

    // Warm L2 for the epilogue's c_in tile (64 rows; mask avoids OOB rows).
    l2_prefetch(c_in + (size_t)(m0 + (tid & 63)) * HID + nh0);

    // per-lane ldmatrix base offsets + constant swizzle mask (row&7)<<4.
    // fp16 A fragment -> matrices ROWS-first; B fragment -> matrices COLS-first.
    const uint32_t lrowA = (uint32_t)(((lid >> 3) & 1) * 8 + (lid & 7));
    const uint32_t lcolA = (uint32_t)(((lid >> 4) & 1) * 16);
    const uint32_t lrowB = (uint32_t)(((lid >> 4) & 1) * 8 + (lid & 7));
    const uint32_t lcolB = (uint32_t)(((lid >> 3) & 1) * 16);
    const uint32_t xm    = (uint32_t)((lid & 7) << 4);
    const uint32_t aOff = (uint32_t)(wm0 + lrowA) * 128u + lcolA;           // A tile
    const uint32_t bOff = STAGE_A + (uint32_t)(wn0 + lrowB) * 128u + lcolB; // B tile

    float acc[2][8][4];
#pragma unroll
    for (int i = 0; i < 2; i++)
#pragma unroll
        for (int j = 0; j < 8; j++)
#pragma unroll
            for (int r = 0; r < 4; r++) acc[i][j][r] = 0.0f;

    // prologue: preload chunks 0,1,2 into stages 0,1,2 (3 committed groups)
    load_stage(sbase, 0, 0, m0, nh0, tid); cp_commit();
    load_stage(sbase, 1, 1, m0, nh0, tid); cp_commit();
    load_stage(sbase, 2, 2, m0, nh0, tid); cp_commit();

    int s = 0;
    for (int k = 0; k < KI; k++) {
        // Pending (valid) groups: {k, k+1, k+2}. wait<2> -> chunk k COMPLETE
        // with 2-chunk slack; empty tail commits keep the count aligned.
        if (k + 2 < KI)      cp_wait<2>();
        else if (k + 1 < KI) cp_wait<1>();
        else                 cp_wait<0>();
        // Single barrier: (a) chunk-k stores visible to all warps,
        // (b) all warps finished chunk k-1 -> stage (s+3)%4 reusable.
        __syncthreads();

        // Issue chunk k+3 BEFORE compute: two full MMA bodies of lead time.
        if (k + 3 < KI) {
            int sl = s + 3; if (sl >= NSTAGE) sl -= NSTAGE;
            load_stage(sbase, sl, k + 3, m0, nh0, tid);
        }
        cp_commit();   // commit every iter (empty groups keep count aligned)

        const uint32_t stA = sbase + (uint32_t)s * STAGE_BYTES + aOff;
        const uint32_t stB = sbase + (uint32_t)s * STAGE_BYTES + bOff;
#pragma unroll
        for (int ks = 0; ks < 4; ks++) {   // 4 k16 steps of 32B each
            uint32_t af[2][4], bf[4][4];
#pragma unroll
            for (int i = 0; i < 2; i++)
                ldsm4(af[i], (stA + (uint32_t)(i * 2048 + ks * 32)) ^ xm);
#pragma unroll
            for (int jp = 0; jp < 4; jp++)
                ldsm4(bf[jp], (stB + (uint32_t)(jp * 2048 + ks * 32)) ^ xm);
#pragma unroll
            for (int i = 0; i < 2; i++)
#pragma unroll
                for (int j = 0; j < 8; j++)
                    mma_f16(acc[i][j], af[i], &bf[j >> 1][(j & 1) * 2]);
        }

        s++; if (s == NSTAGE) s = 0;
    }

    // ------------------------------------------------------------------
    // Register-only LSTM epilogue.
    // acc[i][j][r]: row = m0+wm0+i*16 + lid/4 + (r>>1)*8
    //               smem col = wn0 + j*8 + 2*(lid&3) + (r&1)
    // smem col c -> gate=(c>>4)&3, hcol=((c>>6)&1)*16 + (c&15)
    // ------------------------------------------------------------------
    const int wHc = (wid & 1) * 16;
#pragma unroll
    for (int i = 0; i < 2; i++) {
#pragma unroll
        for (int rh = 0; rh < 2; rh++) {
            const int m = m0 + wm0 + i * 16 + (lid >> 2) + rh * 8;
            const float* crow = c_in + (size_t)m * HID + nh0;
            float* hrow  = h_out + (size_t)m * HID + nh0;
            float* corow = c_out + (size_t)m * HID + nh0;
#pragma unroll
            for (int hb = 0; hb < 2; hb++) {
#pragma unroll
                for (int cc = 0; cc < 2; cc++) {
                    const int hc   = wHc + hb * 8 + (lid & 3) * 2 + cc;
                    const int colb = wn0 + hb * 8 + (lid & 3) * 2 + cc; // gate 0 col
                    const int rr   = rh * 2 + cc;
                    float zi = acc[i][0 + hb][rr] + s_bias[colb];
                    float zf = acc[i][2 + hb][rr] + s_bias[colb + 16];
                    float zg = acc[i][4 + hb][rr] + s_bias[colb + 32];
                    float zo = acc[i][6 + hb][rr] + s_bias[colb + 48];
                    float iv = sigm(zi), fv = sigm(zf);
                    float gv = tanhe(zg), ov = sigm(zo);
                    float cn = fv * crow[hc] + iv * gv;
                    corow[hc] = cn;
                    hrow[hc]  = ov * tanhe(cn);
                }
            }
        }
    }
}

// ---------------------------------------------------------------------------
// Launcher
// ---------------------------------------------------------------------------
extern "C" void kernel_launch(void* const* d_in, const int* in_sizes, int n_in,
                              void* d_out, int out_size) {
    (void)in_sizes; (void)n_in; (void)out_size;
    const float* x  = (const float*)d_in[0];
    const float* h  = (const float*)d_in[1];
    const float* c  = (const float*)d_in[2];
    const float* Wx = (const float*)d_in[3];
    const float* bx = (const float*)d_in[4];
    const float* Wh = (const float*)d_in[5];
    float* out   = (float*)d_out;
    float* h_out = out;
    float* c_out = out + (size_t)BATCH * HID;

    cudaFuncSetAttribute(lstm_gemm_kernel,
                         cudaFuncAttributeMaxDynamicSharedMemorySize, DYN_SMEM);

    // Merged prep: fp16-round + pack A=[x|h] and B=W^T in ONE launch
    pack_ab_kernel<<<PACKA_BLOCKS + PACKB_BLOCKS, 256>>>(x, h, Wx, Wh);

    // Fused GEMM + LSTM epilogue (m0 fastest -> co-resident CTAs share B slice)
    lstm_gemm_kernel<<<dim3(BATCH / BM, HID / BNH), 128, DYN_SMEM>>>(
        c, bx, h_out, c_out);
}

// round 17
// speedup vs baseline: 1.3839x; 1.3839x over previous
#include <cuda_runtime.h>
#include <cuda_fp16.h>
#include <cstdint>

#define DINLINE __device__ __forceinline__

// ---------------------------------------------------------------------------
// Problem constants
// ---------------------------------------------------------------------------
constexpr int BATCH = 8192;
constexpr int HID   = 1024;
constexpr int KDIM  = 2048;               // I + H
constexpr int NTOT  = 4096;               // 4 gates * HID

constexpr int BM  = 64;                   // CTA M tile (3 CTAs/SM)
constexpr int BN  = 128;                  // CTA N tile (4 gates x 32 h-cols)
constexpr int BNH = 32;                   // h-columns per CTA
constexpr int KC  = 64;                   // K per chunk (64 fp16 = 128 B/row)
constexpr int KI  = KDIM / KC;            // 32 chunks

constexpr int NSTAGE      = 3;
constexpr int STAGE_A     = BM * 128;     // 8 KB
constexpr int STAGE_B     = BN * 128;     // 16 KB
constexpr int STAGE_BYTES = STAGE_A + STAGE_B;            // 24 KB
constexpr int DYN_SMEM    = 1024 + NSTAGE * STAGE_BYTES;  // ~73 KB -> 3 CTAs/SM

// Merged prep kernel block split
constexpr int PACKA_BLOCKS = (BATCH * KDIM / 8) / 256;    // 8192 (8 halves/thr)
constexpr int PACKB_BLOCKS = (KDIM / 32) * (NTOT / 32);   // 8192

// Scratch (allocation-free rule: __device__ globals)
__device__ __half g_A[(size_t)BATCH * KDIM];   // 32 MB: fp16 [x|h]
__device__ __half g_B[(size_t)NTOT * KDIM];    // 16 MB: fp16 W^T (K-major)
// 48 MB total: L2-resident (measured DRAM 5%).

// ---------------------------------------------------------------------------
// PTX helpers (base PTX only: cp.async / ldmatrix / mma.sync)
// ---------------------------------------------------------------------------
DINLINE uint32_t smem_u32(const void* p) {
    uint32_t a;
    asm("{ .reg .u64 t; cvta.to.shared.u64 t, %1; cvt.u32.u64 %0, t; }"
        : "=r"(a) : "l"(p));
    return a;
}

DINLINE void cp16(uint32_t dst, const void* src) {
    asm volatile("cp.async.cg.shared.global [%0], [%1], 16;"
                 :: "r"(dst), "l"(src) : "memory");
}
DINLINE void cp_commit() { asm volatile("cp.async.commit_group;" ::: "memory"); }
template <int N> DINLINE void cp_wait() {
    asm volatile("cp.async.wait_group %0;" :: "n"(N) : "memory");
}

DINLINE void l2_prefetch(const void* p) {
    asm volatile("prefetch.global.L2 [%0];" :: "l"(p));
}

// ldmatrix.x4 on fp16: lane l of each 8x8 b16 matrix gets the 4B word
// [row=l/4][pair=l%4] -- exactly one fp16 mma fragment register.
DINLINE void ldsm4(uint32_t* r, uint32_t addr) {
    asm volatile("ldmatrix.sync.aligned.m8n8.x4.shared.b16 {%0,%1,%2,%3}, [%4];"
                 : "=r"(r[0]), "=r"(r[1]), "=r"(r[2]), "=r"(r[3]) : "r"(addr));
}

// fp16 m16n8k16: 2048 MACs/instr, f32 accumulate.
DINLINE void mma_f16(float* d, const uint32_t* a, const uint32_t* b) {
    asm("mma.sync.aligned.m16n8k16.row.col.f32.f16.f16.f32 "
        "{%0,%1,%2,%3}, {%4,%5,%6,%7}, {%8,%9}, {%0,%1,%2,%3};"
        : "+f"(d[0]), "+f"(d[1]), "+f"(d[2]), "+f"(d[3])
        : "r"(a[0]), "r"(a[1]), "r"(a[2]), "r"(a[3]), "r"(b[0]), "r"(b[1]));
}

DINLINE uint32_t SWZ(uint32_t b) { return b ^ ((b >> 3) & 0x70); }

DINLINE float sigm(float x)  { return __fdividef(1.0f, 1.0f + __expf(-x)); }
DINLINE float tanhe(float x) { return 1.0f - __fdividef(2.0f, __expf(2.0f * x) + 1.0f); }

// ---------------------------------------------------------------------------
// Merged prep kernel: blocks [0, PACKA_BLOCKS) pack A=[x|h] -> fp16; the rest
// pack B=W^T (K-major) -> fp16. fp16 rn rounding == tf32 mantissa -> error
// profile identical to the measured 2.01e-4 config.
// ---------------------------------------------------------------------------
__global__ void pack_ab_kernel(const float* __restrict__ x,
                               const float* __restrict__ h,
                               const float* __restrict__ Wx,
                               const float* __restrict__ Wh) {
    const int tid = threadIdx.x;            // 256 threads
    if (blockIdx.x < PACKA_BLOCKS) {
        // ---- pack A: 8 floats -> 8 halves (16B store) ----
        size_t v = (size_t)blockIdx.x * 256 + tid;   // 8-half group index
        int m = (int)(v >> 8);              // 256 groups per 2048-wide row
        int q = (int)(v & 255);
        const float* src = (q < 128) ? (x + (size_t)m * HID + (size_t)q * 8)
                                     : (h + (size_t)m * HID + (size_t)(q - 128) * 8);
        float4 f0 = ((const float4*)src)[0];
        float4 f1 = ((const float4*)src)[1];
        __half2 r[4];
        r[0] = __floats2half2_rn(f0.x, f0.y);
        r[1] = __floats2half2_rn(f0.z, f0.w);
        r[2] = __floats2half2_rn(f1.x, f1.y);
        r[3] = __floats2half2_rn(f1.z, f1.w);
        *(uint4*)(g_A + v * 8) = *(const uint4*)r;
    } else {
        // ---- pack B: fp16-round + transpose W -> [N, K] ----
        __shared__ float tile[32][33];
        int bb = blockIdx.x - PACKA_BLOCKS;
        int k0 = (bb & 63) * 32;            // 64 k-blocks
        int n0 = (bb >> 6) * 32;            // 128 n-blocks
        int tx = tid & 31, ty = tid >> 5;   // (32, 8)
#pragma unroll
        for (int i = 0; i < 32; i += 8) {
            int k = k0 + ty + i;
            float v = (k < 1024) ? Wx[(size_t)k * NTOT + n0 + tx]
                                 : Wh[(size_t)(k - 1024) * NTOT + n0 + tx];
            tile[ty + i][tx] = v;
        }
        __syncthreads();
#pragma unroll
        for (int i = 0; i < 32; i += 8) {
            int n = n0 + ty + i;
            g_B[(size_t)n * KDIM + k0 + tx] = __float2half_rn(tile[tx][ty + i]);
        }
    }
}

// ---------------------------------------------------------------------------
// Fused GEMM + LSTM epilogue (cp.async + ldmatrix + mma.sync.f16)
// R15 mainloop VERBATIM (proven fastest): single barrier, wait<1> -> sync ->
// issue k+2 -> compute k, 3 stages, 3 CTAs/SM. [R16's .ca/4-stage both dead.]
// ---------------------------------------------------------------------------
// Grid = (m fastest, nh slowest): all 128 CTAs of one nh0 column reuse the
// SAME B slice in L2 while A streams once.
//
// B smem row r (0..127) holds global N row:
//   n(r) = ((r>>4)&3)*1024 + nh0 + (r&15) + ((r>>6)&1)*16
// so each warp's 64 columns = {i,f,g,o} x 16 h-cols and each THREAD holds all
// four gate values for its (m, hcol) pairs -> register-only LSTM epilogue.
DINLINE void load_stage(uint32_t sbase, int s, int kc, int m0, int nh0, int tid) {
    const uint32_t sA = sbase + (uint32_t)s * STAGE_BYTES;
    const uint32_t sB = sA + STAGE_A;
    const __half* gA = g_A + (size_t)m0 * KDIM + (size_t)kc * KC;
    const __half* gB = g_B + (size_t)kc * KC;
#pragma unroll
    for (int i = 0; i < 4; i++) {          // A: 64 rows x 128B (64 fp16)
        int ch = tid + (i << 7);
        int r = ch >> 3, kb = ch & 7;
        uint32_t off = (uint32_t)(r * 128 + kb * 16);
        cp16(sA + SWZ(off), (const char*)(gA + (size_t)r * KDIM) + kb * 16);
    }
#pragma unroll
    for (int i = 0; i < 8; i++) {          // B: 128 gate-interleaved N rows x 128B
        int ch = tid + (i << 7);
        int r = ch >> 3, kb = ch & 7;
        int n = ((r >> 4) & 3) * 1024 + nh0 + (r & 15) + ((r >> 6) & 1) * 16;
        uint32_t off = (uint32_t)(r * 128 + kb * 16);
        cp16(sB + SWZ(off), (const char*)(gB + (size_t)n * KDIM) + kb * 16);
    }
}

__global__ void __launch_bounds__(128, 3)
lstm_gemm_kernel(const float* __restrict__ c_in, const float* __restrict__ bx,
                 float* __restrict__ h_out, float* __restrict__ c_out) {
    extern __shared__ __align__(16) char dynsmem[];
    __shared__ float s_bias[BN];

    const int tid = threadIdx.x;
    const int wid = tid >> 5;
    const int lid = tid & 31;
    const int m0  = blockIdx.x * BM;    // m fastest (proven best)
    const int nh0 = blockIdx.y * BNH;

    const int wm0 = (wid >> 1) * 32;   // warp M offset (2x2 warp grid, 32x64 tiles)
    const int wn0 = (wid & 1) * 64;    // warp N offset (smem B column space)

    uint32_t sbase = (smem_u32(dynsmem) + 1023u) & ~1023u;

    // bias cache, ordered identically to B smem columns
    {
        int r = tid;
        int n = ((r >> 4) & 3) * 1024 + nh0 + (r & 15) + ((r >> 6) & 1) * 16;
        s_bias[r] = bx[n];
    }

    // Warm L2 for the epilogue's c_in tile (64 rows; mask avoids OOB rows).
    l2_prefetch(c_in + (size_t)(m0 + (tid & 63)) * HID + nh0);

    // per-lane ldmatrix base offsets + constant swizzle mask (row&7)<<4.
    // fp16 A fragment -> matrices ROWS-first; B fragment -> matrices COLS-first.
    const uint32_t lrowA = (uint32_t)(((lid >> 3) & 1) * 8 + (lid & 7));
    const uint32_t lcolA = (uint32_t)(((lid >> 4) & 1) * 16);
    const uint32_t lrowB = (uint32_t)(((lid >> 4) & 1) * 8 + (lid & 7));
    const uint32_t lcolB = (uint32_t)(((lid >> 3) & 1) * 16);
    const uint32_t xm    = (uint32_t)((lid & 7) << 4);
    const uint32_t aOff = (uint32_t)(wm0 + lrowA) * 128u + lcolA;           // A tile
    const uint32_t bOff = STAGE_A + (uint32_t)(wn0 + lrowB) * 128u + lcolB; // B tile

    float acc[2][8][4];
#pragma unroll
    for (int i = 0; i < 2; i++)
#pragma unroll
        for (int j = 0; j < 8; j++)
#pragma unroll
            for (int r = 0; r < 4; r++) acc[i][j][r] = 0.0f;

    // prologue: preload chunks 0,1 into stages 0,1 (2 committed groups)
    load_stage(sbase, 0, 0, m0, nh0, tid); cp_commit();
    load_stage(sbase, 1, 1, m0, nh0, tid); cp_commit();

    int s = 0;
    for (int k = 0; k < KI; k++) {
        // Pending groups: {k, k+1} (valid ones). wait<1> -> chunk k COMPLETE.
        if (k + 1 < KI) cp_wait<1>(); else cp_wait<0>();
        // Single barrier: (a) chunk-k stores visible to all warps,
        // (b) all warps finished chunk k-1 -> stage (s+2)%3 reusable.
        __syncthreads();

        // Issue chunk k+2 BEFORE compute; 3 co-resident CTAs + full MMA body
        // cover its L2 latency.
        if (k + 2 < KI) {
            int sl = s + 2; if (sl >= NSTAGE) sl -= NSTAGE;
            load_stage(sbase, sl, k + 2, m0, nh0, tid);
        }
        cp_commit();   // commit every iter (empty groups keep count aligned)

        const uint32_t stA = sbase + (uint32_t)s * STAGE_BYTES + aOff;
        const uint32_t stB = sbase + (uint32_t)s * STAGE_BYTES + bOff;
#pragma unroll
        for (int ks = 0; ks < 4; ks++) {   // 4 k16 steps of 32B each
            uint32_t af[2][4], bf[4][4];
#pragma unroll
            for (int i = 0; i < 2; i++)
                ldsm4(af[i], (stA + (uint32_t)(i * 2048 + ks * 32)) ^ xm);
#pragma unroll
            for (int jp = 0; jp < 4; jp++)
                ldsm4(bf[jp], (stB + (uint32_t)(jp * 2048 + ks * 32)) ^ xm);
#pragma unroll
            for (int i = 0; i < 2; i++)
#pragma unroll
                for (int j = 0; j < 8; j++)
                    mma_f16(acc[i][j], af[i], &bf[j >> 1][(j & 1) * 2]);
        }

        s++; if (s == NSTAGE) s = 0;
    }

    // ------------------------------------------------------------------
    // Register-only LSTM epilogue, float2-vectorized stores.
    // acc[i][j][r]: row = m0+wm0+i*16 + lid/4 + (r>>1)*8
    //               smem col = wn0 + j*8 + 2*(lid&3) + (r&1)
    // cc=0,1 are ADJACENT h-columns with acc components rr=rh*2+cc ->
    // fuse each pair into one float2 load (c_in) and two float2 stores.
    // ------------------------------------------------------------------
    const int wHc = (wid & 1) * 16;
#pragma unroll
    for (int i = 0; i < 2; i++) {
#pragma unroll
        for (int rh = 0; rh < 2; rh++) {
            const int m = m0 + wm0 + i * 16 + (lid >> 2) + rh * 8;
            const float* crow = c_in + (size_t)m * HID + nh0;
            float* hrow  = h_out + (size_t)m * HID + nh0;
            float* corow = c_out + (size_t)m * HID + nh0;
#pragma unroll
            for (int hb = 0; hb < 2; hb++) {
                const int hcB  = wHc + hb * 8 + (lid & 3) * 2;   // even -> 8B aligned
                const int colB = wn0 + hb * 8 + (lid & 3) * 2;   // gate 0 col base
                const float2 cold = *(const float2*)(crow + hcB);
                float2 hnew, cnew;
#pragma unroll
                for (int cc = 0; cc < 2; cc++) {
                    const int rr = rh * 2 + cc;
                    float zi = acc[i][0 + hb][rr] + s_bias[colB + cc];
                    float zf = acc[i][2 + hb][rr] + s_bias[colB + cc + 16];
                    float zg = acc[i][4 + hb][rr] + s_bias[colB + cc + 32];
                    float zo = acc[i][6 + hb][rr] + s_bias[colB + cc + 48];
                    float iv = sigm(zi), fv = sigm(zf);
                    float gv = tanhe(zg), ov = sigm(zo);
                    float cv = (cc == 0) ? cold.x : cold.y;
                    float cn = fv * cv + iv * gv;
                    float hn = ov * tanhe(cn);
                    if (cc == 0) { cnew.x = cn; hnew.x = hn; }
                    else         { cnew.y = cn; hnew.y = hn; }
                }
                *(float2*)(corow + hcB) = cnew;
                *(float2*)(hrow  + hcB) = hnew;
            }
        }
    }
}

// ---------------------------------------------------------------------------
// Launcher
// ---------------------------------------------------------------------------
extern "C" void kernel_launch(void* const* d_in, const int* in_sizes, int n_in,
                              void* d_out, int out_size) {
    (void)in_sizes; (void)n_in; (void)out_size;
    const float* x  = (const float*)d_in[0];
    const float* h  = (const float*)d_in[1];
    const float* c  = (const float*)d_in[2];
    const float* Wx = (const float*)d_in[3];
    const float* bx = (const float*)d_in[4];
    const float* Wh = (const float*)d_in[5];
    float* out   = (float*)d_out;
    float* h_out = out;
    float* c_out = out + (size_t)BATCH * HID;

    cudaFuncSetAttribute(lstm_gemm_kernel,
                         cudaFuncAttributeMaxDynamicSharedMemorySize, DYN_SMEM);

    // Merged prep: fp16-round + pack A=[x|h] and B=W^T in ONE launch
    pack_ab_kernel<<<PACKA_BLOCKS + PACKB_BLOCKS, 256>>>(x, h, Wx, Wh);

    // Fused GEMM + LSTM epilogue (m0 fastest -> co-resident CTAs share B slice)
    lstm_gemm_kernel<<<dim3(BATCH / BM, HID / BNH), 128, DYN_SMEM>>>(
        c, bx, h_out, c_out);
}